// round 3
// baseline (speedup 1.0000x reference)
#include <cuda_runtime.h>
#include <cuda_bf16.h>
#include <math.h>
#include <stdint.h>

// Problem constants
#define Bb   4
#define Ssz  4096
#define Dd   2048
#define DFFz 8192
#define KSEL 512
#define MROWS (Bb*KSEL)   // 2048 selected rows

// GEMM tiling
#define TM 128
#define TN 128
#define TK 32
#define STAGES 3
#define AS_STRIDE 40                   // bf16 elems per smem row (80B, conflict-free)
#define STAGE_ELEMS (2*128*AS_STRIDE)  // A + B per stage = 10240 elems
#define SMEM_BYTES (STAGES*STAGE_ELEMS*2)   // 61440

// ---------------- scratch (device globals; no runtime allocation) ----------
__device__ __align__(1024) float g_logits[Bb*Ssz];
__device__ __align__(1024) int   g_tokens[MROWS];
__device__ __align__(1024) float g_rw[MROWS];
__device__ __align__(1024) __nv_bfloat16 g_fxb[(size_t)MROWS*Dd];    // 8 MB
__device__ __align__(1024) __nv_bfloat16 g_hb [(size_t)MROWS*DFFz];  // 32 MB
__device__ __align__(1024) __nv_bfloat16 g_w1t[(size_t)DFFz*Dd];     // 32 MB [N,K]
__device__ __align__(1024) __nv_bfloat16 g_w2t[(size_t)Dd*DFFz];     // 32 MB [N,K]

// ---------------- helpers ----------------------------------------------------
__device__ __forceinline__ uint32_t smem_u32(const void* p){
    uint32_t a;
    asm("{ .reg .u64 t; cvta.to.shared.u64 t, %1; cvt.u32.u64 %0, t; }" : "=r"(a) : "l"(p));
    return a;
}
__device__ __forceinline__ unsigned int fmono(float f){
    unsigned int b = __float_as_uint(f);
    return (b & 0x80000000u) ? ~b : (b | 0x80000000u);
}
__device__ __forceinline__ float gelu_exact(float z){
    return 0.5f * z * (1.0f + erff(z * 0.70710678118654752f));
}
__device__ __forceinline__ void ldmx4(uint32_t* r, uint32_t addr){
    asm volatile("ldmatrix.sync.aligned.m8n8.x4.shared.b16 {%0,%1,%2,%3}, [%4];"
        : "=r"(r[0]), "=r"(r[1]), "=r"(r[2]), "=r"(r[3]) : "r"(addr));
}
__device__ __forceinline__ void mma16816(float* c, const uint32_t* a, uint32_t b0, uint32_t b1){
    asm volatile("mma.sync.aligned.m16n8k16.row.col.f32.bf16.bf16.f32 "
        "{%0,%1,%2,%3}, {%4,%5,%6,%7}, {%8,%9}, {%0,%1,%2,%3};"
        : "+f"(c[0]), "+f"(c[1]), "+f"(c[2]), "+f"(c[3])
        : "r"(a[0]), "r"(a[1]), "r"(a[2]), "r"(a[3]), "r"(b0), "r"(b1));
}
__device__ __forceinline__ void cp16(uint32_t dst, const void* src){
    asm volatile("cp.async.cg.shared.global [%0], [%1], 16;" :: "r"(dst), "l"(src));
}

// ---------------- router -----------------------------------------------------
__global__ void router_kernel(const float* __restrict__ x,
                              const float* __restrict__ Wr,
                              const float* __restrict__ br){
    int row  = blockIdx.x * (blockDim.x >> 5) + (threadIdx.x >> 5);
    int lane = threadIdx.x & 31;
    const float4* xr = reinterpret_cast<const float4*>(x + (size_t)row * Dd);
    const float4* w4 = reinterpret_cast<const float4*>(Wr);
    float s = 0.f;
    #pragma unroll 4
    for (int i = lane; i < Dd/4; i += 32){
        float4 a = xr[i], w = w4[i];
        s += a.x*w.x + a.y*w.y + a.z*w.z + a.w*w.w;
    }
    #pragma unroll
    for (int o = 16; o > 0; o >>= 1) s += __shfl_down_sync(0xffffffffu, s, o);
    if (lane == 0) g_logits[row] = s + br[0];
}

// ---------------- top-k via per-batch bitonic sort ---------------------------
__global__ void topk_kernel(){
    __shared__ unsigned long long keys[Ssz];
    __shared__ float sval[KSEL];
    __shared__ int   sidx[KSEL];
    __shared__ float red [KSEL];
    int b   = blockIdx.x;
    int tid = threadIdx.x;

    for (int s = tid; s < Ssz; s += blockDim.x){
        unsigned int m = fmono(g_logits[b*Ssz + s]);
        keys[s] = ((unsigned long long)m << 32) | (unsigned int)(~(unsigned int)s);
    }
    __syncthreads();
    for (int k = 2; k <= Ssz; k <<= 1){
        for (int j = k >> 1; j > 0; j >>= 1){
            for (int t = tid; t < Ssz; t += blockDim.x){
                int ixj = t ^ j;
                if (ixj > t){
                    bool up = ((t & k) == 0);
                    unsigned long long a = keys[t], c = keys[ixj];
                    bool sw = up ? (a > c) : (a < c);
                    if (sw){ keys[t] = c; keys[ixj] = a; }
                }
            }
            __syncthreads();
        }
    }
    if (tid < KSEL){
        unsigned long long key = keys[Ssz - 1 - tid];
        unsigned int u = (unsigned int)(key >> 32);
        float v = (u & 0x80000000u) ? __uint_as_float(u & 0x7FFFFFFFu)
                                    : __uint_as_float(~u);
        sval[tid] = v;
        sidx[tid] = (int)(~(unsigned int)key);
    }
    __syncthreads();
    float vmax = sval[0];
    if (tid < KSEL) red[tid] = expf(sval[tid] - vmax);
    __syncthreads();
    for (int st = KSEL/2; st > 0; st >>= 1){
        if (tid < st) red[tid] += red[tid + st];
        __syncthreads();
    }
    float denom = red[0];
    if (tid < KSEL){
        g_tokens[b*KSEL + tid] = sidx[tid];
        g_rw   [b*KSEL + tid] = expf(sval[tid] - vmax) / denom;
    }
}

// ---------------- gather selected rows into FX (fp32 -> bf16) ----------------
__global__ void gather_kernel(const float* __restrict__ x){
    int m = blockIdx.x;
    int b = m >> 9;
    int t = g_tokens[m];
    const float4* src = reinterpret_cast<const float4*>(x + ((size_t)b*Ssz + t) * Dd);
    uint2* dst = reinterpret_cast<uint2*>(g_fxb + (size_t)m * Dd);
    for (int i = threadIdx.x; i < Dd/4; i += blockDim.x){
        float4 v = src[i];
        uint2 o;
        asm("cvt.rn.bf16x2.f32 %0, %1, %2;" : "=r"(o.x) : "f"(v.y), "f"(v.x));
        asm("cvt.rn.bf16x2.f32 %0, %1, %2;" : "=r"(o.y) : "f"(v.w), "f"(v.z));
        dst[i] = o;
    }
}

// ---------------- W [K,N] fp32 -> Wt [N,K] bf16 ------------------------------
__global__ void transpose_cvt_kernel(const float* __restrict__ W,
                                     __nv_bfloat16* __restrict__ Wt,
                                     int K, int N){
    __shared__ float t[32][33];
    int n0 = blockIdx.x * 32, k0 = blockIdx.y * 32;
    int tx = threadIdx.x & 31, ty = threadIdx.x >> 5;   // 256 threads: 32x8
    #pragma unroll
    for (int r = 0; r < 4; r++)
        t[ty + 8*r][tx] = W[(size_t)(k0 + ty + 8*r) * N + n0 + tx];
    __syncthreads();
    #pragma unroll
    for (int r = 0; r < 4; r++)
        Wt[(size_t)(n0 + ty + 8*r) * K + k0 + tx] = __float2bfloat16(t[tx][ty + 8*r]);
}

// ---------------- HMMA bf16 GEMM (mma.sync m16n8k16) --------------------------
// EPI==1: g_hb = bf16(gelu(FX @ W1t^T + b1))
// EPI==2: out[b,t,:] = x[b,t,:] + rw*(H @ W2t^T + b2)
template<int EPI>
__global__ void __launch_bounds__(256)
mma_gemm(const __nv_bfloat16* __restrict__ Aglob,
         const __nv_bfloat16* __restrict__ Bglob,
         const float* __restrict__ bias,
         const float* __restrict__ xin, float* __restrict__ out,
         int K)
{
    extern __shared__ __nv_bfloat16 sm[];
    const int tid = threadIdx.x, lane = tid & 31, wid = tid >> 5;
    const int bm = blockIdx.y, bn = blockIdx.x;
    const int wm = wid >> 2, wn = wid & 3;       // 2 x 4 warps, warptile 64x32
    const uint32_t sbase = smem_u32(sm);
    const int KT = K / TK;

    const __nv_bfloat16* Ag = Aglob + (size_t)(bm * TM) * K;
    const __nv_bfloat16* Bg = Bglob + (size_t)(bn * TN) * K;

    float acc[4][4][4];
    #pragma unroll
    for (int i = 0; i < 4; i++)
        #pragma unroll
        for (int j = 0; j < 4; j++)
            #pragma unroll
            for (int q = 0; q < 4; q++) acc[i][j][q] = 0.f;

    auto ld_stage = [&](int kt, int s){
        #pragma unroll
        for (int i = 0; i < 2; i++){
            int ch = tid + i*256;               // 512 chunks per operand
            int r = ch >> 2, c = ch & 3;
            uint32_t da = sbase + (uint32_t)(s*STAGE_ELEMS + r*AS_STRIDE + c*8) * 2;
            uint32_t db = da + 128*AS_STRIDE*2;
            cp16(da, Ag + (size_t)r*K + kt*TK + c*8);
            cp16(db, Bg + (size_t)r*K + kt*TK + c*8);
        }
        asm volatile("cp.async.commit_group;" ::: "memory");
    };

    ld_stage(0, 0);
    ld_stage(1, 1);

    const int arow = lane & 15, achk = lane >> 4;
    const int brow = (lane & 7) + ((lane >> 4) & 1) * 8;
    const int bchk = (lane >> 3) & 1;

    int s = 0;
    for (int kt = 0; kt < KT; kt++){
        if (kt == KT - 1) asm volatile("cp.async.wait_group 0;" ::: "memory");
        else              asm volatile("cp.async.wait_group 1;" ::: "memory");
        __syncthreads();
        if (kt + 2 < KT){
            int s2 = s + 2; if (s2 >= STAGES) s2 -= STAGES;
            ld_stage(kt + 2, s2);
        }

        uint32_t aoff = sbase + (uint32_t)(s*STAGE_ELEMS) * 2;
        uint32_t boff = aoff + 128*AS_STRIDE*2;
        #pragma unroll
        for (int ks = 0; ks < 2; ks++){
            uint32_t afr[4][4], bfr[2][4];
            #pragma unroll
            for (int mi = 0; mi < 4; mi++)
                ldmx4(afr[mi], aoff + (uint32_t)((wm*64 + mi*16 + arow)*AS_STRIDE + ks*16 + achk*8) * 2);
            #pragma unroll
            for (int ni = 0; ni < 2; ni++)
                ldmx4(bfr[ni], boff + (uint32_t)((wn*32 + ni*16 + brow)*AS_STRIDE + ks*16 + bchk*8) * 2);
            #pragma unroll
            for (int mi = 0; mi < 4; mi++)
                #pragma unroll
                for (int nj = 0; nj < 4; nj++)
                    mma16816(acc[mi][nj], afr[mi], bfr[nj>>1][(nj&1)*2], bfr[nj>>1][(nj&1)*2+1]);
        }
        s++; if (s >= STAGES) s = 0;
    }

    // ---------------- epilogue ----------------
    const int crow = lane >> 2, ccol = (lane & 3) * 2;
    if (EPI == 1){
        #pragma unroll
        for (int mi = 0; mi < 4; mi++){
            #pragma unroll
            for (int h = 0; h < 2; h++){
                int m = bm*TM + wm*64 + mi*16 + crow + h*8;
                uint32_t* hrow = reinterpret_cast<uint32_t*>(g_hb + (size_t)m * DFFz);
                #pragma unroll
                for (int nj = 0; nj < 4; nj++){
                    int n = bn*TN + wn*32 + nj*8 + ccol;
                    float v0 = gelu_exact(acc[mi][nj][h*2+0] + bias[n]);
                    float v1 = gelu_exact(acc[mi][nj][h*2+1] + bias[n+1]);
                    uint32_t p;
                    asm("cvt.rn.bf16x2.f32 %0, %1, %2;" : "=r"(p) : "f"(v1), "f"(v0));
                    hrow[n >> 1] = p;
                }
            }
        }
    } else {
        #pragma unroll
        for (int mi = 0; mi < 4; mi++){
            #pragma unroll
            for (int h = 0; h < 2; h++){
                int m = bm*TM + wm*64 + mi*16 + crow + h*8;
                int bb = m >> 9;
                int t  = g_tokens[m];
                float w = g_rw[m];
                size_t base = ((size_t)bb * Ssz + t) * (size_t)Dd;
                #pragma unroll
                for (int nj = 0; nj < 4; nj++){
                    int n = bn*TN + wn*32 + nj*8 + ccol;
                    float2 o;
                    o.x = xin[base + n]     + w * (acc[mi][nj][h*2+0] + bias[n]);
                    o.y = xin[base + n + 1] + w * (acc[mi][nj][h*2+1] + bias[n+1]);
                    *reinterpret_cast<float2*>(out + base + n) = o;
                }
            }
        }
    }
}

// ---------------- launch -------------------------------------------------------
extern "C" void kernel_launch(void* const* d_in, const int* in_sizes, int n_in,
                              void* d_out, int out_size){
    const float* x  = (const float*)d_in[0];
    const float* Wr = (const float*)d_in[1];
    const float* br = (const float*)d_in[2];
    const float* W1 = (const float*)d_in[3];
    const float* b1 = (const float*)d_in[4];
    const float* W2 = (const float*)d_in[5];
    const float* b2 = (const float*)d_in[6];
    float* out = (float*)d_out;

    cudaFuncSetAttribute(mma_gemm<1>, cudaFuncAttributeMaxDynamicSharedMemorySize, SMEM_BYTES);
    cudaFuncSetAttribute(mma_gemm<2>, cudaFuncAttributeMaxDynamicSharedMemorySize, SMEM_BYTES);

    // pass-through copy of x into out (non-selected tokens unchanged)
    cudaMemcpyAsync(out, x, (size_t)Bb*Ssz*Dd*sizeof(float),
                    cudaMemcpyDeviceToDevice, 0);

    router_kernel<<<(Bb*Ssz)/8, 256>>>(x, Wr, br);
    topk_kernel<<<Bb, 1024>>>();
    gather_kernel<<<MROWS, 256>>>(x);

    transpose_cvt_kernel<<<dim3(DFFz/32, Dd/32), 256>>>(W1, g_w1t, Dd, DFFz);
    transpose_cvt_kernel<<<dim3(Dd/32, DFFz/32), 256>>>(W2, g_w2t, DFFz, Dd);

    mma_gemm<1><<<dim3(DFFz/TN, MROWS/TM), 256, SMEM_BYTES>>>(
        g_fxb, g_w1t, b1, nullptr, nullptr, Dd);
    mma_gemm<2><<<dim3(Dd/TN, MROWS/TM), 256, SMEM_BYTES>>>(
        g_hb, g_w2t, b2, x, out, DFFz);
}

// round 4
// speedup vs baseline: 6.9854x; 6.9854x over previous
#include <cuda_runtime.h>
#include <math.h>
#include <stdint.h>

// Problem constants
#define Bb   4
#define Ssz  4096
#define Dd   2048
#define DFFz 8192
#define KSEL 512
#define MROWS (Bb*KSEL)   // 2048 selected rows

// GEMM tiling: CTA 128x128, TK=16, thread 8x8, 256 threads
#define TK 16
#define STAGES 3
#define STAGE_F32 (2*TK*128)                  // A(16x128) + B(16x128) = 4096 f32
#define SMEM_BYTES (STAGES*STAGE_F32*4)       // 49152

// ---------------- scratch (device globals; no runtime allocation) ----------
__device__ __align__(1024) float g_logits[Bb*Ssz];
__device__ __align__(1024) int   g_tokens[MROWS];
__device__ __align__(1024) float g_rw[MROWS];
__device__ __align__(1024) float g_fxT[(size_t)Dd*MROWS];    // [K=2048][M=2048] 16MB
__device__ __align__(1024) float g_hT [(size_t)DFFz*MROWS];  // [K=8192][M=2048] 64MB

// ---------------- helpers ----------------------------------------------------
__device__ __forceinline__ uint32_t smem_u32(const void* p){
    uint32_t a;
    asm("{ .reg .u64 t; cvta.to.shared.u64 t, %1; cvt.u32.u64 %0, t; }" : "=r"(a) : "l"(p));
    return a;
}
__device__ __forceinline__ unsigned int fmono(float f){
    unsigned int b = __float_as_uint(f);
    return (b & 0x80000000u) ? ~b : (b | 0x80000000u);
}
__device__ __forceinline__ float gelu_exact(float z){
    return 0.5f * z * (1.0f + erff(z * 0.70710678118654752f));
}
__device__ __forceinline__ unsigned long long pack2(float lo, float hi){
    unsigned long long r;
    asm("mov.b64 %0, {%1, %2};" : "=l"(r) : "f"(lo), "f"(hi));
    return r;
}
__device__ __forceinline__ void ffma2(unsigned long long &c, unsigned long long a, unsigned long long b){
    asm("fma.rn.f32x2 %0, %1, %2, %0;" : "+l"(c) : "l"(a), "l"(b));
}
__device__ __forceinline__ float2 unpack2(unsigned long long v){
    float lo, hi;
    asm("mov.b64 {%0, %1}, %2;" : "=f"(lo), "=f"(hi) : "l"(v));
    return make_float2(lo, hi);
}
__device__ __forceinline__ void cp16(uint32_t dst, const void* src){
    asm volatile("cp.async.cg.shared.global [%0], [%1], 16;" :: "r"(dst), "l"(src));
}

// ---------------- router -----------------------------------------------------
__global__ void router_kernel(const float* __restrict__ x,
                              const float* __restrict__ Wr,
                              const float* __restrict__ br){
    int row  = blockIdx.x * (blockDim.x >> 5) + (threadIdx.x >> 5);
    int lane = threadIdx.x & 31;
    const float4* xr = reinterpret_cast<const float4*>(x + (size_t)row * Dd);
    const float4* w4 = reinterpret_cast<const float4*>(Wr);
    float s = 0.f;
    #pragma unroll 4
    for (int i = lane; i < Dd/4; i += 32){
        float4 a = xr[i], w = w4[i];
        s += a.x*w.x + a.y*w.y + a.z*w.z + a.w*w.w;
    }
    #pragma unroll
    for (int o = 16; o > 0; o >>= 1) s += __shfl_down_sync(0xffffffffu, s, o);
    if (lane == 0) g_logits[row] = s + br[0];
}

// ---------------- top-k via per-batch bitonic sort ---------------------------
__global__ void topk_kernel(){
    __shared__ unsigned long long keys[Ssz];
    __shared__ float sval[KSEL];
    __shared__ int   sidx[KSEL];
    __shared__ float red [KSEL];
    int b   = blockIdx.x;
    int tid = threadIdx.x;

    for (int s = tid; s < Ssz; s += blockDim.x){
        unsigned int m = fmono(g_logits[b*Ssz + s]);
        keys[s] = ((unsigned long long)m << 32) | (unsigned int)(~(unsigned int)s);
    }
    __syncthreads();
    for (int k = 2; k <= Ssz; k <<= 1){
        for (int j = k >> 1; j > 0; j >>= 1){
            for (int t = tid; t < Ssz; t += blockDim.x){
                int ixj = t ^ j;
                if (ixj > t){
                    bool up = ((t & k) == 0);
                    unsigned long long a = keys[t], c = keys[ixj];
                    bool sw = up ? (a > c) : (a < c);
                    if (sw){ keys[t] = c; keys[ixj] = a; }
                }
            }
            __syncthreads();
        }
    }
    if (tid < KSEL){
        unsigned long long key = keys[Ssz - 1 - tid];
        unsigned int u = (unsigned int)(key >> 32);
        float v = (u & 0x80000000u) ? __uint_as_float(u & 0x7FFFFFFFu)
                                    : __uint_as_float(~u);
        sval[tid] = v;
        sidx[tid] = (int)(~(unsigned int)key);
    }
    __syncthreads();
    float vmax = sval[0];
    if (tid < KSEL) red[tid] = expf(sval[tid] - vmax);
    __syncthreads();
    for (int st = KSEL/2; st > 0; st >>= 1){
        if (tid < st) red[tid] += red[tid + st];
        __syncthreads();
    }
    float denom = red[0];
    if (tid < KSEL){
        g_tokens[b*KSEL + tid] = sidx[tid];
        g_rw   [b*KSEL + tid] = expf(sval[tid] - vmax) / denom;
    }
}

// ---------------- gather selected rows into FX^T [K][M] ----------------------
// 32x32 tiles: coalesced gather read, transposed coalesced write.
__global__ void gatherT_kernel(const float* __restrict__ x){
    __shared__ float t[32][33];
    int m0 = blockIdx.x * 32;   // selected-row dim
    int k0 = blockIdx.y * 32;   // feature dim
    int tx = threadIdx.x & 31, ty = threadIdx.x >> 5;   // 32x8
    #pragma unroll
    for (int r = 0; r < 4; r++){
        int m = m0 + ty + 8*r;
        int b = m >> 9;
        int tok = g_tokens[m];
        t[ty + 8*r][tx] = x[((size_t)b*Ssz + tok)*Dd + k0 + tx];
    }
    __syncthreads();
    #pragma unroll
    for (int r = 0; r < 4; r++)
        g_fxT[(size_t)(k0 + ty + 8*r) * MROWS + m0 + tx] = t[tx][ty + 8*r];
}

// ---------------- f32x2 SIMT GEMM with cp.async, both operands K-major -------
// A^T: [K][M] (our transposed activations), B: [K][N] (weights as-is)
// EPI==1: g_hT[n][m] = gelu(sum + b1[n])          (K=Dd,  N=DFFz)
// EPI==2: out[b,tok(m),n] = x[...] + rw[m]*(sum + b2[n])   (K=DFFz, N=Dd)
template<int EPI>
__global__ void __launch_bounds__(256, 2)
gemm_kernel(const float* __restrict__ AT, const float* __restrict__ Bw,
            const float* __restrict__ bias,
            const float* __restrict__ xin, float* __restrict__ out,
            int M, int N, int K)
{
    extern __shared__ float sm[];
    const int tid = threadIdx.x;
    const int tx = tid & 15, ty = tid >> 4;
    const int bn = blockIdx.x, bm = blockIdx.y;
    const uint32_t sbase = smem_u32(sm);
    const int KT = K / TK;

    const float* Ag = AT + (size_t)0 * M + bm * 128;   // + k*M
    const float* Bg = Bw + bn * 128;                    // + k*N

    unsigned long long acc[8][4];
    #pragma unroll
    for (int i = 0; i < 8; i++)
        #pragma unroll
        for (int j = 0; j < 4; j++) acc[i][j] = 0ull;

    // cp.async one stage: A 16x128 then B 16x128; 512 chunks of 16B total... (each 2048 f32)
    auto ld_stage = [&](int kt, int s){
        uint32_t base = sbase + (uint32_t)(s * STAGE_F32) * 4;
        {   // A: 128 chunks x ... 16 rows * 128 f32 = 2048 f32 = 512B*... 128 f32/row = 32 chunks/row
            int ch = tid;                    // 256 threads, 512 chunks -> 2 each
            #pragma unroll
            for (int i = 0; i < 2; i++, ch += 256){
                int kl = ch >> 5, mc = ch & 31;
                cp16(base + (uint32_t)(kl*128 + mc*4)*4,
                     Ag + (size_t)(kt*TK + kl)*M + mc*4);
            }
        }
        {   // B
            uint32_t bb = base + (uint32_t)(TK*128)*4;
            int ch = tid;
            #pragma unroll
            for (int i = 0; i < 2; i++, ch += 256){
                int kl = ch >> 5, nc = ch & 31;
                cp16(bb + (uint32_t)(kl*128 + nc*4)*4,
                     Bg + (size_t)(kt*TK + kl)*N + nc*4);
            }
        }
        asm volatile("cp.async.commit_group;" ::: "memory");
    };

    ld_stage(0, 0);
    ld_stage(1, 1);

    int s = 0;
    for (int kt = 0; kt < KT; kt++){
        if (kt == KT - 1) asm volatile("cp.async.wait_group 0;" ::: "memory");
        else              asm volatile("cp.async.wait_group 1;" ::: "memory");
        __syncthreads();
        if (kt + 2 < KT){
            int s2 = s + 2; if (s2 >= STAGES) s2 -= STAGES;
            ld_stage(kt + 2, s2);
        }

        const float* As = sm + s * STAGE_F32;
        const float* Bs = As + TK*128;
        #pragma unroll
        for (int kk = 0; kk < TK; kk++){
            float4 a0 = *reinterpret_cast<const float4*>(As + kk*128 + ty*8);
            float4 a1 = *reinterpret_cast<const float4*>(As + kk*128 + ty*8 + 4);
            // B: two scattered float4 chunks: cols tx*4 and tx*4+64 (conflict-free)
            const unsigned long long* bp0 =
                reinterpret_cast<const unsigned long long*>(Bs + kk*128 + tx*4);
            const unsigned long long* bp1 =
                reinterpret_cast<const unsigned long long*>(Bs + kk*128 + tx*4 + 64);
            unsigned long long b0 = bp0[0], b1 = bp0[1], b2 = bp1[0], b3 = bp1[1];
            float av[8] = {a0.x, a0.y, a0.z, a0.w, a1.x, a1.y, a1.z, a1.w};
            #pragma unroll
            for (int i = 0; i < 8; i++){
                unsigned long long ap = pack2(av[i], av[i]);
                ffma2(acc[i][0], ap, b0);
                ffma2(acc[i][1], ap, b1);
                ffma2(acc[i][2], ap, b2);
                ffma2(acc[i][3], ap, b3);
            }
        }
        s++; if (s >= STAGES) s = 0;
    }

    // ---------------- epilogue ----------------
    const int m0 = bm*128 + ty*8;
    // thread's n cols: {n0a+0..3} and {n0a+64..67}
    const int n0a = bn*128 + tx*4;
    float bva[4], bvb[4];
    #pragma unroll
    for (int c = 0; c < 4; c++){ bva[c] = bias[n0a + c]; bvb[c] = bias[n0a + 64 + c]; }

    if (EPI == 1){
        // write H^T[n][m]: per n, 8 m-values from acc[0..7]
        #pragma unroll
        for (int p = 0; p < 4; p++){
            #pragma unroll
            for (int h = 0; h < 2; h++){
                int n = (p < 2) ? (n0a + p*2 + h) : (n0a + 64 + (p-2)*2 + h);
                float bb = (p < 2) ? bva[p*2 + h] : bvb[(p-2)*2 + h];
                float v[8];
                #pragma unroll
                for (int i = 0; i < 8; i++){
                    float2 u = unpack2(acc[i][p]);
                    v[i] = gelu_exact((h ? u.y : u.x) + bb);
                }
                float* dst = g_hT + (size_t)n * MROWS + m0;
                *reinterpret_cast<float4*>(dst)     = make_float4(v[0], v[1], v[2], v[3]);
                *reinterpret_cast<float4*>(dst + 4) = make_float4(v[4], v[5], v[6], v[7]);
            }
        }
    } else {
        #pragma unroll
        for (int i = 0; i < 8; i++){
            int m = m0 + i;
            int bb = m >> 9;
            int tok = g_tokens[m];
            float w = g_rw[m];
            size_t base = ((size_t)bb * Ssz + tok) * (size_t)Dd;
            float2 q0 = unpack2(acc[i][0]), q1 = unpack2(acc[i][1]);
            float2 q2 = unpack2(acc[i][2]), q3 = unpack2(acc[i][3]);
            const float4 xa = *reinterpret_cast<const float4*>(xin + base + n0a);
            const float4 xb = *reinterpret_cast<const float4*>(xin + base + n0a + 64);
            float4 oa, ob;
            oa.x = xa.x + w*(q0.x + bva[0]);  oa.y = xa.y + w*(q0.y + bva[1]);
            oa.z = xa.z + w*(q1.x + bva[2]);  oa.w = xa.w + w*(q1.y + bva[3]);
            ob.x = xb.x + w*(q2.x + bvb[0]);  ob.y = xb.y + w*(q2.y + bvb[1]);
            ob.z = xb.z + w*(q3.x + bvb[2]);  ob.w = xb.w + w*(q3.y + bvb[3]);
            *reinterpret_cast<float4*>(out + base + n0a)      = oa;
            *reinterpret_cast<float4*>(out + base + n0a + 64) = ob;
        }
    }
}

// ---------------- launch -------------------------------------------------------
extern "C" void kernel_launch(void* const* d_in, const int* in_sizes, int n_in,
                              void* d_out, int out_size){
    const float* x  = (const float*)d_in[0];
    const float* Wr = (const float*)d_in[1];
    const float* br = (const float*)d_in[2];
    const float* W1 = (const float*)d_in[3];
    const float* b1 = (const float*)d_in[4];
    const float* W2 = (const float*)d_in[5];
    const float* b2 = (const float*)d_in[6];
    float* out = (float*)d_out;

    cudaFuncSetAttribute(gemm_kernel<1>, cudaFuncAttributeMaxDynamicSharedMemorySize, SMEM_BYTES);
    cudaFuncSetAttribute(gemm_kernel<2>, cudaFuncAttributeMaxDynamicSharedMemorySize, SMEM_BYTES);

    // pass-through copy of x into out (non-selected tokens unchanged)
    cudaMemcpyAsync(out, x, (size_t)Bb*Ssz*Dd*sizeof(float),
                    cudaMemcpyDeviceToDevice, 0);

    router_kernel<<<(Bb*Ssz)/8, 256>>>(x, Wr, br);
    topk_kernel<<<Bb, 1024>>>();
    gatherT_kernel<<<dim3(MROWS/32, Dd/32), 256>>>(x);

    float *p_fxT, *p_hT;
    cudaGetSymbolAddress((void**)&p_fxT, g_fxT);
    cudaGetSymbolAddress((void**)&p_hT,  g_hT);

    // GEMM1: [MROWS x DFFz] = fx @ W1 ; A^T = g_fxT, writes g_hT (transposed)
    gemm_kernel<1><<<dim3(DFFz/128, MROWS/128), 256, SMEM_BYTES>>>(
        p_fxT, W1, b1, nullptr, nullptr, MROWS, DFFz, Dd);
    // GEMM2: [MROWS x Dd] = H @ W2 ; A^T = g_hT, scatter into out
    gemm_kernel<2><<<dim3(Dd/128, MROWS/128), 256, SMEM_BYTES>>>(
        p_hT, W2, b2, x, out, MROWS, Dd, DFFz);
}